// round 4
// baseline (speedup 1.0000x reference)
#include <cuda_runtime.h>

#define TT 65536
#define HH 50
#define RR 200      // 4*H gate rows
#define PC 208      // padded row stride of precompute buffer (floats)
#define NTH 224     // 7 warps

// Precomputed: P[t][0..199] = W_ih1[:, :7] @ x_t[:7] + b_ih1 + b_hh1 ; P[t][200] = x_t[7] (act_dist)
__device__ float g_P[(size_t)TT * PC];

__device__ __forceinline__ unsigned long long pk2(float a, float b){
    unsigned long long r; asm("mov.b64 %0, {%1, %2};" : "=l"(r) : "f"(a), "f"(b)); return r;
}
__device__ __forceinline__ void fma2(unsigned long long& acc, unsigned long long a, unsigned long long b){
    asm("fma.rn.f32x2 %0, %1, %2, %0;" : "+l"(acc) : "l"(a), "l"(b));
}
__device__ __forceinline__ void upk2(unsigned long long v, float& x, float& y){
    asm("mov.b64 {%0, %1}, %2;" : "=f"(x), "=f"(y) : "l"(v));
}

// ---------------------------------------------------------------------------
// Kernel 1: parallel precompute of the err-independent part of layer-1 gates.
// ---------------------------------------------------------------------------
__global__ void precompute_kernel(const float* __restrict__ x,
                                  const float* __restrict__ Wih1,
                                  const float* __restrict__ bih1,
                                  const float* __restrict__ bhh1)
{
    int t = blockIdx.x;
    int j = threadIdx.x;
    const float* xr = x + t * 8;
    if (j < RR){
        float acc = bih1[j] + bhh1[j];
        const float* w = Wih1 + j * 8;
        #pragma unroll
        for (int k = 0; k < 7; k++) acc = fmaf(w[k], xr[k], acc);
        g_P[(size_t)t * PC + j] = acc;
    } else if (j == RR){
        g_P[(size_t)t * PC + RR] = xr[7];   // act_dist
    }
}

// ---------------------------------------------------------------------------
// Kernel 2: persistent single-block sequential LSTM scan.
// Thread tid<200 owns gate row tid; rows [0,50)=i, [50,100)=f, [100,150)=g,
// [150,200)=o. Weights live in registers as f32x2 pairs. h1/h2 in shared.
// ---------------------------------------------------------------------------
__global__ void __launch_bounds__(NTH, 1) lstm_kernel(
    const float* __restrict__ Wih1, const float* __restrict__ Whh1,
    const float* __restrict__ Wih2, const float* __restrict__ Whh2,
    const float* __restrict__ bih2, const float* __restrict__ bhh2,
    const float* __restrict__ Wout, const float* __restrict__ bout,
    float* __restrict__ out)
{
    const int tid = threadIdx.x;
    const bool isrow = tid < RR;
    const bool isg = (tid >= 2*HH && tid < 3*HH);      // tanh rows
    const float sact = isg ? 2.f : 1.f;                // act = sact/(1+exp(-sact*v)) - oact
    const float oact = isg ? 1.f : 0.f;                // sigmoid (s=1,o=0) or tanh (s=2,o=1)

    // --- load this row's weights into registers, packed as f32x2 pairs ---
    unsigned long long wh1[26], wi2[26], wh2[26];
    float werr = 0.f, b2 = 0.f;
    if (isrow){
        werr = Wih1[tid * 8 + 7];                       // weight on the err input
        const float* a = Whh1 + tid * HH;
        const float* b = Wih2 + tid * HH;
        const float* c = Whh2 + tid * HH;
        #pragma unroll
        for (int k = 0; k < 25; k++){
            wh1[k] = pk2(a[2*k], a[2*k+1]);
            wi2[k] = pk2(b[2*k], b[2*k+1]);
            wh2[k] = pk2(c[2*k], c[2*k+1]);
        }
        wh1[25] = 0ull; wi2[25] = 0ull; wh2[25] = 0ull; // pad pair (h[50],h[51])
        b2 = bih2[tid] + bhh2[tid];
    } else {
        #pragma unroll
        for (int k = 0; k < 26; k++){ wh1[k]=0ull; wi2[k]=0ull; wh2[k]=0ull; }
    }
    float wout_r = (tid < HH) ? Wout[tid] : 0.f;
    float bo = bout[0];

    __shared__ __align__(16) float sh_h1[56];
    __shared__ __align__(16) float sh_h2[56];
    __shared__ float sh_g[RR];
    __shared__ float sh_red[2];

    if (tid < 56){ sh_h1[tid] = 0.f; sh_h2[tid] = 0.f; }   // incl. zero padding

    float c1 = 0.f, c2 = 0.f, err = 0.f;
    float p_cur  = isrow ? g_P[tid] : 0.f;
    float ad_cur = g_P[RR];
    __syncthreads();

    for (int t = 0; t < TT; t++){
        // prefetch next step's precomputed row (L2 hit; consumed next iter)
        int tn = (t + 1 < TT) ? (t + 1) : t;
        const float* Pn = g_P + (size_t)tn * PC;
        float p_next  = isrow ? Pn[tid] : 0.f;
        float ad_next = Pn[RR];

        // ---- phase 1: layer-1 gates ----
        if (isrow){
            unsigned long long a0 = 0ull, a1 = 0ull;
            const ulonglong2* s = (const ulonglong2*)sh_h1;
            #pragma unroll
            for (int k = 0; k < 13; k++){
                ulonglong2 v = s[k];
                fma2(a0, wh1[2*k],   v.x);
                fma2(a1, wh1[2*k+1], v.y);
            }
            float x0,y0,x1,y1; upk2(a0,x0,y0); upk2(a1,x1,y1);
            float v = (x0 + x1) + (y0 + y1) + fmaf(err, werr, p_cur);
            float act = __fdividef(sact, 1.f + __expf(-sact * v)) - oact;
            sh_g[tid] = act;
        }
        __syncthreads();

        // ---- phase 2: layer-1 cell update ----
        if (tid < HH){
            float gi = sh_g[tid], gf = sh_g[HH+tid], gg = sh_g[2*HH+tid], go = sh_g[3*HH+tid];
            c1 = fmaf(gf, c1, gi * gg);
            float th = __fdividef(2.f, 1.f + __expf(-2.f * c1)) - 1.f;
            sh_h1[tid] = go * th;
        }
        __syncthreads();

        // ---- phase 3: layer-2 gates ----
        if (isrow){
            unsigned long long a0=0ull, a1=0ull, b0=0ull, b1=0ull;
            const ulonglong2* s1 = (const ulonglong2*)sh_h1;
            const ulonglong2* s2 = (const ulonglong2*)sh_h2;
            #pragma unroll
            for (int k = 0; k < 13; k++){
                ulonglong2 u = s1[k];
                ulonglong2 w = s2[k];
                fma2(a0, wi2[2*k],   u.x);
                fma2(a1, wi2[2*k+1], u.y);
                fma2(b0, wh2[2*k],   w.x);
                fma2(b1, wh2[2*k+1], w.y);
            }
            float x0,y0,x1,y1,z0,u0,z1,u1;
            upk2(a0,x0,y0); upk2(a1,x1,y1); upk2(b0,z0,u0); upk2(b1,z1,u1);
            float v = ((x0+x1) + (y0+y1)) + ((z0+z1) + (u0+u1)) + b2;
            float act = __fdividef(sact, 1.f + __expf(-sact * v)) - oact;
            sh_g[tid] = act;
        }
        __syncthreads();

        // ---- phase 4: layer-2 cell update + output reduction ----
        float py = 0.f;
        if (tid < HH){
            float gi = sh_g[tid], gf = sh_g[HH+tid], gg = sh_g[2*HH+tid], go = sh_g[3*HH+tid];
            c2 = fmaf(gf, c2, gi * gg);
            float th = __fdividef(2.f, 1.f + __expf(-2.f * c2)) - 1.f;
            float h = go * th;
            sh_h2[tid] = h;
            py = wout_r * h;
        }
        if (tid < 64){                      // warps 0,1 fully participate
            py += __shfl_down_sync(0xffffffffu, py, 16);
            py += __shfl_down_sync(0xffffffffu, py, 8);
            py += __shfl_down_sync(0xffffffffu, py, 4);
            py += __shfl_down_sync(0xffffffffu, py, 2);
            py += __shfl_down_sync(0xffffffffu, py, 1);
            if ((tid & 31) == 0) sh_red[tid >> 5] = py;
        }
        __syncthreads();

        // ---- scalar output + feedback err (computed redundantly by all) ----
        float y = sh_red[0] + sh_red[1] + bo;
        if (tid == 0) out[t] = y;
        err = fmaf(0.9f, err, 0.1f * (ad_cur - y));
        p_cur = p_next; ad_cur = ad_next;
    }
}

extern "C" void kernel_launch(void* const* d_in, const int* in_sizes, int n_in,
                              void* d_out, int out_size)
{
    const float* x    = (const float*)d_in[0];
    const float* Wih1 = (const float*)d_in[1];
    const float* Whh1 = (const float*)d_in[2];
    const float* bih1 = (const float*)d_in[3];
    const float* bhh1 = (const float*)d_in[4];
    const float* Wih2 = (const float*)d_in[5];
    const float* Whh2 = (const float*)d_in[6];
    const float* bih2 = (const float*)d_in[7];
    const float* bhh2 = (const float*)d_in[8];
    const float* Wout = (const float*)d_in[9];
    const float* bout = (const float*)d_in[10];
    float* out = (float*)d_out;

    precompute_kernel<<<TT, NTH>>>(x, Wih1, bih1, bhh1);
    lstm_kernel<<<1, NTH>>>(Wih1, Whh1, Wih2, Whh2, bih2, bhh2, Wout, bout, out);
}

// round 7
// speedup vs baseline: 1.0823x; 1.0823x over previous
#include <cuda_runtime.h>

#define TT 65536
#define HH 50
#define RR 200      // 4*H gate rows
#define PC 208      // padded row stride of precompute buffer (floats)
#define PNT 224     // precompute threads
#define LT 400      // lstm threads: 50 elements x 4 gates x 2 halves

// Precomputed: P[t][0..199] = W_ih1[:, :7] @ x_t[:7] + b_ih1 + b_hh1 ; P[t][200] = x_t[7]
__device__ float g_P[(size_t)TT * PC];

static __device__ __forceinline__ unsigned long long pk2(float a, float b){
    unsigned long long r; asm("mov.b64 %0, {%1, %2};" : "=l"(r) : "f"(a), "f"(b)); return r;
}
static __device__ __forceinline__ void fma2(unsigned long long& acc, unsigned long long a, unsigned long long b){
    asm("fma.rn.f32x2 %0, %1, %2, %0;" : "+l"(acc) : "l"(a), "l"(b));
}
static __device__ __forceinline__ float upksum(unsigned long long v){
    float x, y; asm("mov.b64 {%0, %1}, %2;" : "=f"(x), "=f"(y) : "l"(v)); return x + y;
}

// ---------------------------------------------------------------------------
// Kernel 1: parallel precompute of the err-independent part of layer-1 gates.
// ---------------------------------------------------------------------------
__global__ void precompute_kernel(const float* __restrict__ x,
                                  const float* __restrict__ Wih1,
                                  const float* __restrict__ bih1,
                                  const float* __restrict__ bhh1)
{
    int t = blockIdx.x;
    int j = threadIdx.x;
    const float* xr = x + t * 8;
    if (j < RR){
        float acc = bih1[j] + bhh1[j];
        const float* w = Wih1 + j * 8;
        #pragma unroll
        for (int k = 0; k < 7; k++) acc = fmaf(w[k], xr[k], acc);
        g_P[(size_t)t * PC + j] = acc;
    } else if (j == RR){
        g_P[(size_t)t * PC + RR] = xr[7];   // act_dist
    }
}

// ---------------------------------------------------------------------------
// Kernel 2: persistent single-block sequential LSTM scan.
// Thread tid = e*8 + q*2 + hf:
//   e  in [0,50) : hidden element (8-lane group)
//   q  in [0,4)  : gate (i,f,g,o)
//   hf in [0,2)  : half of the 50-wide dot product (elements [26*hf, 26*hf+26))
// Weights register-resident as f32x2 pairs. Halves combined via shfl_xor(1);
// the 4 gates of an element exchanged via a 3-shfl butterfly -> cell update
// happens in-register with no extra barrier. 2 __syncthreads per step.
// y and err computed redundantly by all threads (deterministic).
// ---------------------------------------------------------------------------
__global__ void __launch_bounds__(LT, 1) lstm_kernel(
    const float* __restrict__ Wih1, const float* __restrict__ Whh1,
    const float* __restrict__ Wih2, const float* __restrict__ Whh2,
    const float* __restrict__ bih2, const float* __restrict__ bhh2,
    const float* __restrict__ Wout, const float* __restrict__ bout,
    float* __restrict__ out)
{
    const int tid = threadIdx.x;
    const int e   = tid >> 3;
    const int sub = tid & 7;
    const int q   = sub >> 1;
    const int hf  = sub & 1;
    const int row = q * HH + e;
    const unsigned gmask = 0xFFu << ((tid & 31) & 24);   // this lane's 8-lane group

    const float sact = (q == 2) ? 2.f : 1.f;   // act = sact/(1+exp(-sact*v)) - oact
    const float oact = (q == 2) ? 1.f : 0.f;   // sigmoid for i,f,o; tanh for g

    // ---- register-resident weights (half rows, f32x2 packed, zero-padded) ----
    unsigned long long wh1[13], wi2[13], wh2[13], wo[25];
    {
        const float* a = Whh1 + row * HH;
        const float* b = Wih2 + row * HH;
        const float* c = Whh2 + row * HH;
        #pragma unroll
        for (int k = 0; k < 13; k++){
            int i0 = 26 * hf + 2 * k, i1 = i0 + 1;
            float a0 = (i0 < HH) ? a[i0] : 0.f, a1 = (i1 < HH) ? a[i1] : 0.f;
            float b0 = (i0 < HH) ? b[i0] : 0.f, b1 = (i1 < HH) ? b[i1] : 0.f;
            float c0 = (i0 < HH) ? c[i0] : 0.f, c1v = (i1 < HH) ? c[i1] : 0.f;
            wh1[k] = pk2(a0, a1);
            wi2[k] = pk2(b0, b1);
            wh2[k] = pk2(c0, c1v);
        }
        #pragma unroll
        for (int k = 0; k < 25; k++) wo[k] = pk2(Wout[2*k], Wout[2*k+1]);
    }
    const float werr = Wih1[row * 8 + 7];
    const float b2   = bih2[row] + bhh2[row];
    const float bo   = bout[0];

    // ping-pong h buffers, padded to 64 (entries 50..63 stay zero)
    __shared__ __align__(16) float sh1[2][64];
    __shared__ __align__(16) float sh2[2][64];
    if (tid < 64){ sh1[0][tid] = 0.f; sh1[1][tid] = 0.f; sh2[0][tid] = 0.f; sh2[1][tid] = 0.f; }

    float c1 = 0.f, c2 = 0.f, err = 0.f;
    float p_cur  = g_P[row];
    float ad_cur = g_P[RR];
    __syncthreads();

    int cb = 0;                              // cb = t&1 (write buffer)
    for (int t = 0; t < TT; t++){
        const int pb = cb ^ 1;               // previous step's buffer

        // prefetch next step's precomputed gate bias + act_dist (consumed at t+1)
        const int tn = (t + 1 < TT) ? (t + 1) : t;
        const float p_next  = g_P[(size_t)tn * PC + row];
        const float ad_next = g_P[(size_t)tn * PC + RR];

        // ================= phase A: layer-1 gates + cell =================
        {
            unsigned long long a0 = 0ull, a1 = 0ull;
            const float* hb = sh1[pb] + 26 * hf;
            #pragma unroll
            for (int k = 0; k < 13; k++){
                unsigned long long v = *(const unsigned long long*)(hb + 2*k);
                if (k & 1) fma2(a1, wh1[k], v); else fma2(a0, wh1[k], v);
            }
            float s = upksum(a0) + upksum(a1);
            s += __shfl_xor_sync(gmask, s, 1);                 // combine halves
            float v = s + fmaf(werr, err, p_cur);
            float act = __fdividef(sact, 1.f + __expf(-sact * v)) - oact;

            // butterfly: gather all 4 gates of element e into every lane
            float g1 = __shfl_xor_sync(gmask, act, 2);         // gate q^1
            float g2 = __shfl_xor_sync(gmask, act, 4);         // gate q^2
            float g3 = __shfl_xor_sync(gmask, g1, 4);          // gate q^3
            float gi, gf, gg, go;
            if      (q == 0){ gi = act; gf = g1;  gg = g2;  go = g3;  }
            else if (q == 1){ gi = g1;  gf = act; gg = g3;  go = g2;  }
            else if (q == 2){ gi = g2;  gf = g3;  gg = act; go = g1;  }
            else            { gi = g3;  gf = g2;  gg = g1;  go = act; }
            c1 = fmaf(gf, c1, gi * gg);
            float th = __fdividef(2.f, 1.f + __expf(-2.f * c1)) - 1.f;
            float h1v = go * th;
            if (sub == 0) sh1[cb][e] = h1v;
        }
        __syncthreads();

        // ================= phase B: layer-2 gates + cell =================
        {
            unsigned long long a0 = 0ull, a1 = 0ull, d0 = 0ull, d1 = 0ull;
            const float* hb1 = sh1[cb] + 26 * hf;
            const float* hb2 = sh2[pb] + 26 * hf;
            #pragma unroll
            for (int k = 0; k < 13; k++){
                unsigned long long u = *(const unsigned long long*)(hb1 + 2*k);
                unsigned long long w = *(const unsigned long long*)(hb2 + 2*k);
                if (k & 1){ fma2(a1, wi2[k], u); fma2(d1, wh2[k], w); }
                else      { fma2(a0, wi2[k], u); fma2(d0, wh2[k], w); }
            }
            float s = (upksum(a0) + upksum(a1)) + (upksum(d0) + upksum(d1));
            s += __shfl_xor_sync(gmask, s, 1);
            float v = s + b2;
            float act = __fdividef(sact, 1.f + __expf(-sact * v)) - oact;

            float g1 = __shfl_xor_sync(gmask, act, 2);
            float g2 = __shfl_xor_sync(gmask, act, 4);
            float g3 = __shfl_xor_sync(gmask, g1, 4);
            float gi, gf, gg, go;
            if      (q == 0){ gi = act; gf = g1;  gg = g2;  go = g3;  }
            else if (q == 1){ gi = g1;  gf = act; gg = g3;  go = g2;  }
            else if (q == 2){ gi = g2;  gf = g3;  gg = act; go = g1;  }
            else            { gi = g3;  gf = g2;  gg = g1;  go = act; }
            c2 = fmaf(gf, c2, gi * gg);
            float th = __fdividef(2.f, 1.f + __expf(-2.f * c2)) - 1.f;
            float h2v = go * th;
            if (sub == 0) sh2[cb][e] = h2v;
        }
        __syncthreads();

        // ====== phase C: y + err, redundantly in every thread (no barrier) ======
        {
            unsigned long long acc0 = 0ull, acc1 = 0ull, acc2 = 0ull, acc3 = 0ull;
            const float4* hb = (const float4*)sh2[cb];
            #pragma unroll
            for (int k = 0; k < 12; k++){
                float4 vv = hb[k];                                 // elements 4k..4k+3
                unsigned long long lo = pk2(vv.x, vv.y);
                unsigned long long hi = pk2(vv.z, vv.w);
                switch (k & 1){
                    case 0: fma2(acc0, wo[2*k], lo); fma2(acc1, wo[2*k+1], hi); break;
                    default: fma2(acc2, wo[2*k], lo); fma2(acc3, wo[2*k+1], hi); break;
                }
            }
            unsigned long long last = *(const unsigned long long*)(sh2[cb] + 48);
            fma2(acc0, wo[24], last);
            float y = ((upksum(acc0) + upksum(acc1)) + (upksum(acc2) + upksum(acc3))) + bo;
            if (tid == 0) out[t] = y;
            err = fmaf(0.9f, err, 0.1f * (ad_cur - y));
        }

        p_cur = p_next; ad_cur = ad_next; cb ^= 1;
    }
}

extern "C" void kernel_launch(void* const* d_in, const int* in_sizes, int n_in,
                              void* d_out, int out_size)
{
    const float* x    = (const float*)d_in[0];
    const float* Wih1 = (const float*)d_in[1];
    const float* Whh1 = (const float*)d_in[2];
    const float* bih1 = (const float*)d_in[3];
    const float* bhh1 = (const float*)d_in[4];
    const float* Wih2 = (const float*)d_in[5];
    const float* Whh2 = (const float*)d_in[6];
    const float* bih2 = (const float*)d_in[7];
    const float* bhh2 = (const float*)d_in[8];
    const float* Wout = (const float*)d_in[9];
    const float* bout = (const float*)d_in[10];
    float* out = (float*)d_out;

    precompute_kernel<<<TT, PNT>>>(x, Wih1, bih1, bhh1);
    lstm_kernel<<<1, LT>>>(Wih1, Whh1, Wih2, Whh2, bih2, bhh2, Wout, bout, out);
}

// round 11
// speedup vs baseline: 1.2619x; 1.1659x over previous
#include <cuda_runtime.h>

#define TT 65536
#define HH 50
#define RR 200      // 4*H gate rows
#define PC 208      // padded row stride of precompute buffer (floats)
#define PNT 224     // precompute threads
#define LT 400      // lstm threads: 50 elements x 4 gates x 2 halves

// Precomputed: P[t][0..199] = W_ih1[:, :7] @ x_t[:7] + b_ih1 + b_hh1 ; P[t][200] = x_t[7]
__device__ float g_P[(size_t)TT * PC];

static __device__ __forceinline__ unsigned long long pk2(float a, float b){
    unsigned long long r; asm("mov.b64 %0, {%1, %2};" : "=l"(r) : "f"(a), "f"(b)); return r;
}
static __device__ __forceinline__ void fma2(unsigned long long& acc, unsigned long long a, unsigned long long b){
    asm("fma.rn.f32x2 %0, %1, %2, %0;" : "+l"(acc) : "l"(a), "l"(b));
}
static __device__ __forceinline__ void add2(unsigned long long& acc, unsigned long long a){
    asm("add.rn.f32x2 %0, %0, %1;" : "+l"(acc) : "l"(a));
}
static __device__ __forceinline__ float upksum(unsigned long long v){
    float x, y; asm("mov.b64 {%0, %1}, %2;" : "=f"(x), "=f"(y) : "l"(v)); return x + y;
}

// ---------------------------------------------------------------------------
// Kernel 1: parallel precompute of the err-independent part of layer-1 gates.
// ---------------------------------------------------------------------------
__global__ void precompute_kernel(const float* __restrict__ x,
                                  const float* __restrict__ Wih1,
                                  const float* __restrict__ bih1,
                                  const float* __restrict__ bhh1)
{
    int t = blockIdx.x;
    int j = threadIdx.x;
    const float* xr = x + t * 8;
    if (j < RR){
        float acc = bih1[j] + bhh1[j];
        const float* w = Wih1 + j * 8;
        #pragma unroll
        for (int k = 0; k < 7; k++) acc = fmaf(w[k], xr[k], acc);
        g_P[(size_t)t * PC + j] = acc;
    } else if (j == RR){
        g_P[(size_t)t * PC + RR] = xr[7];   // act_dist
    }
}

// ---------------------------------------------------------------------------
// Kernel 2: persistent single-block sequential LSTM scan.
// Thread tid = e*8 + q*2 + hf. Weights register-resident (39 u64/thread; no
// per-thread Wout copy, keeping demand under the 128-reg cap -> no spills).
// y is formed from per-element partial products in shared (sh_py, 26 u64 =
// 50 reals + 2 zero pads) summed redundantly by all threads after bar2.
// 2 __syncthreads per step.
// ---------------------------------------------------------------------------
__global__ void __launch_bounds__(LT, 1) lstm_kernel(
    const float* __restrict__ Wih1, const float* __restrict__ Whh1,
    const float* __restrict__ Wih2, const float* __restrict__ Whh2,
    const float* __restrict__ bih2, const float* __restrict__ bhh2,
    const float* __restrict__ Wout, const float* __restrict__ bout,
    float* __restrict__ out)
{
    const int tid = threadIdx.x;
    const int e   = tid >> 3;
    const int sub = tid & 7;
    const int q   = sub >> 1;
    const int hf  = sub & 1;
    const int row = q * HH + e;
    const unsigned gmask = 0xFFu << ((tid & 31) & 24);   // this lane's 8-lane group

    const float sact = (q == 2) ? 2.f : 1.f;   // act = sact/(1+exp(-sact*v)) - oact
    const float oact = (q == 2) ? 1.f : 0.f;   // sigmoid for i,f,o; tanh for g

    // ---- register-resident weights (half rows, f32x2 packed, zero-padded) ----
    unsigned long long wh1[13], wi2[13], wh2[13];
    {
        const float* a = Whh1 + row * HH;
        const float* b = Wih2 + row * HH;
        const float* c = Whh2 + row * HH;
        #pragma unroll
        for (int k = 0; k < 13; k++){
            int i0 = 26 * hf + 2 * k, i1 = i0 + 1;
            float a0 = (i0 < HH) ? a[i0] : 0.f, a1 = (i1 < HH) ? a[i1] : 0.f;
            float b0 = (i0 < HH) ? b[i0] : 0.f, b1 = (i1 < HH) ? b[i1] : 0.f;
            float c0 = (i0 < HH) ? c[i0] : 0.f, c1v = (i1 < HH) ? c[i1] : 0.f;
            wh1[k] = pk2(a0, a1);
            wi2[k] = pk2(b0, b1);
            wh2[k] = pk2(c0, c1v);
        }
    }
    const float werr   = Wih1[row * 8 + 7];
    const float b2     = bih2[row] + bhh2[row];
    const float bo     = bout[0];
    const float wout_e = Wout[e];

    // ping-pong h buffers, padded to 64 (entries 50..63 stay zero)
    __shared__ __align__(16) float sh1[2][64];
    __shared__ __align__(16) float sh2[2][64];
    __shared__ __align__(16) float sh_py[52];            // Wout[e]*h2[e]; 50 real + 2 pad
    if (tid < 64){ sh1[0][tid] = 0.f; sh1[1][tid] = 0.f; sh2[0][tid] = 0.f; sh2[1][tid] = 0.f; }
    if (tid < 2)  sh_py[50 + tid] = 0.f;                 // pad stays zero forever

    float c1 = 0.f, c2 = 0.f, err = 0.f;
    float p_cur  = g_P[row];
    float ad_cur = g_P[RR];
    __syncthreads();

    int cb = 0;                              // cb = t&1 (write buffer)
    for (int t = 0; t < TT; t++){
        const int pb = cb ^ 1;               // previous step's buffer

        // prefetch next step's precomputed gate bias + act_dist (consumed at t+1)
        const int tn = (t + 1 < TT) ? (t + 1) : t;
        const float p_next  = g_P[(size_t)tn * PC + row];
        const float ad_next = g_P[(size_t)tn * PC + RR];

        // ================= phase A: layer-1 gates + cell =================
        {
            unsigned long long a0 = 0ull, a1 = 0ull;
            const float* hb = sh1[pb] + 26 * hf;
            #pragma unroll
            for (int k = 0; k < 13; k++){
                unsigned long long v = *(const unsigned long long*)(hb + 2*k);
                if (k & 1) fma2(a1, wh1[k], v); else fma2(a0, wh1[k], v);
            }
            float s = upksum(a0) + upksum(a1);
            s += __shfl_xor_sync(gmask, s, 1);                 // combine halves
            float v = s + fmaf(werr, err, p_cur);
            float act = __fdividef(sact, 1.f + __expf(-sact * v)) - oact;

            // butterfly: gather all 4 gates of element e into every lane
            float g1 = __shfl_xor_sync(gmask, act, 2);         // gate q^1
            float g2 = __shfl_xor_sync(gmask, act, 4);         // gate q^2
            float g3 = __shfl_xor_sync(gmask, g1, 4);          // gate q^3
            float gi, gf, gg, go;
            if      (q == 0){ gi = act; gf = g1;  gg = g2;  go = g3;  }
            else if (q == 1){ gi = g1;  gf = act; gg = g3;  go = g2;  }
            else if (q == 2){ gi = g2;  gf = g3;  gg = act; go = g1;  }
            else            { gi = g3;  gf = g2;  gg = g1;  go = act; }
            c1 = fmaf(gf, c1, gi * gg);
            float th = __fdividef(2.f, 1.f + __expf(-2.f * c1)) - 1.f;
            float h1v = go * th;
            if (sub == 0) sh1[cb][e] = h1v;
        }
        __syncthreads();

        // ================= phase B: layer-2 gates + cell =================
        {
            unsigned long long a0 = 0ull, a1 = 0ull, d0 = 0ull, d1 = 0ull;
            const float* hb1 = sh1[cb] + 26 * hf;
            const float* hb2 = sh2[pb] + 26 * hf;
            #pragma unroll
            for (int k = 0; k < 13; k++){
                unsigned long long u = *(const unsigned long long*)(hb1 + 2*k);
                unsigned long long w = *(const unsigned long long*)(hb2 + 2*k);
                if (k & 1){ fma2(a1, wi2[k], u); fma2(d1, wh2[k], w); }
                else      { fma2(a0, wi2[k], u); fma2(d0, wh2[k], w); }
            }
            float s = (upksum(a0) + upksum(a1)) + (upksum(d0) + upksum(d1));
            s += __shfl_xor_sync(gmask, s, 1);
            float v = s + b2;
            float act = __fdividef(sact, 1.f + __expf(-sact * v)) - oact;

            float g1 = __shfl_xor_sync(gmask, act, 2);
            float g2 = __shfl_xor_sync(gmask, act, 4);
            float g3 = __shfl_xor_sync(gmask, g1, 4);
            float gi, gf, gg, go;
            if      (q == 0){ gi = act; gf = g1;  gg = g2;  go = g3;  }
            else if (q == 1){ gi = g1;  gf = act; gg = g3;  go = g2;  }
            else if (q == 2){ gi = g2;  gf = g3;  gg = act; go = g1;  }
            else            { gi = g3;  gf = g2;  gg = g1;  go = act; }
            c2 = fmaf(gf, c2, gi * gg);
            float th = __fdividef(2.f, 1.f + __expf(-2.f * c2)) - 1.f;
            float h2v = go * th;
            if (sub == 0){
                sh2[cb][e]  = h2v;
                sh_py[e]    = wout_e * h2v;     // partial product for y
            }
        }
        __syncthreads();

        // ====== phase C: y + err, redundantly in every thread (no barrier) ======
        // Full 50-element reduction = 26 u64 (50 reals + 2 zero pads).
        // sh_py reads complete before bar1 of step t+1, which precedes the next
        // writer (phase B of t+1) -> single-buffered sh_py is race-free.
        {
            unsigned long long s0 = 0ull, s1 = 0ull;
            const unsigned long long* pp = (const unsigned long long*)sh_py;
            #pragma unroll
            for (int k = 0; k < 26; k++){
                if (k & 1) add2(s1, pp[k]); else add2(s0, pp[k]);
            }
            float y = (upksum(s0) + upksum(s1)) + bo;
            if (tid == 0) out[t] = y;
            err = fmaf(0.9f, err, 0.1f * (ad_cur - y));
        }

        p_cur = p_next; ad_cur = ad_next; cb ^= 1;
    }
}

extern "C" void kernel_launch(void* const* d_in, const int* in_sizes, int n_in,
                              void* d_out, int out_size)
{
    const float* x    = (const float*)d_in[0];
    const float* Wih1 = (const float*)d_in[1];
    const float* Whh1 = (const float*)d_in[2];
    const float* bih1 = (const float*)d_in[3];
    const float* bhh1 = (const float*)d_in[4];
    const float* Wih2 = (const float*)d_in[5];
    const float* Whh2 = (const float*)d_in[6];
    const float* bih2 = (const float*)d_in[7];
    const float* bhh2 = (const float*)d_in[8];
    const float* Wout = (const float*)d_in[9];
    const float* bout = (const float*)d_in[10];
    float* out = (float*)d_out;

    precompute_kernel<<<TT, PNT>>>(x, Wih1, bih1, bhh1);
    lstm_kernel<<<1, LT>>>(Wih1, Whh1, Wih2, Whh2, bih2, bhh2, Wout, bout, out);
}

// round 14
// speedup vs baseline: 1.5686x; 1.2430x over previous
#include <cuda_runtime.h>

#define TT 65536
#define HH 50
#define RR 200      // 4*H gate rows
#define PC 208      // padded row stride of precompute buffer (floats)
#define PNT 224     // precompute threads
#define LT 400      // lstm threads: 50 elements x 4 gates x 2 halves

// Precomputed: P[t][0..199] = W_ih1[:, :7] @ x_t[:7] + b_ih1 + b_hh1 ; P[t][200] = x_t[7]
__device__ float g_P[(size_t)TT * PC];

static __device__ __forceinline__ unsigned long long pk2(float a, float b){
    unsigned long long r; asm("mov.b64 %0, {%1, %2};" : "=l"(r) : "f"(a), "f"(b)); return r;
}
static __device__ __forceinline__ void fma2(unsigned long long& acc, unsigned long long a, unsigned long long b){
    asm("fma.rn.f32x2 %0, %1, %2, %0;" : "+l"(acc) : "l"(a), "l"(b));
}
static __device__ __forceinline__ void add2(unsigned long long& acc, unsigned long long a){
    asm("add.rn.f32x2 %0, %0, %1;" : "+l"(acc) : "l"(a));
}
static __device__ __forceinline__ float upksum(unsigned long long v){
    float x, y; asm("mov.b64 {%0, %1}, %2;" : "=f"(x), "=f"(y) : "l"(v)); return x + y;
}
static __device__ __forceinline__ float tanhap(float x){
    float r; asm("tanh.approx.f32 %0, %1;" : "=f"(r) : "f"(x)); return r;
}

// ---------------------------------------------------------------------------
// Kernel 1: parallel precompute of the err-independent part of layer-1 gates.
// ---------------------------------------------------------------------------
__global__ void precompute_kernel(const float* __restrict__ x,
                                  const float* __restrict__ Wih1,
                                  const float* __restrict__ bih1,
                                  const float* __restrict__ bhh1)
{
    int t = blockIdx.x;
    int j = threadIdx.x;
    const float* xr = x + t * 8;
    if (j < RR){
        float acc = bih1[j] + bhh1[j];
        const float* w = Wih1 + j * 8;
        #pragma unroll
        for (int k = 0; k < 7; k++) acc = fmaf(w[k], xr[k], acc);
        g_P[(size_t)t * PC + j] = acc;
    } else if (j == RR){
        g_P[(size_t)t * PC + RR] = xr[7];   // act_dist
    }
}

// ---------------------------------------------------------------------------
// Kernel 2: persistent single-block sequential LSTM scan.
// Thread tid = e*8 + q*2 + hf (e=element, q=gate i/f/g/o, hf=dot half).
// Key structure (per step, 2 barriers):
//   A: v1 = s1pre + werr*err; act; butterfly; cell1 -> sh1[e]      (cheap)
//   B: gates2 dots (h1,h2) AND pre-dot Whh1@h1 for t+1 (reuses the same LDS);
//      act; butterfly; cell2; warp-shfl y-reduction -> 13 partials
//   C: redundant 14-float partial sum -> y, err                    (cheap)
// All activations via single-MUFU tanh.approx (sigmoid = 0.5*tanh(0.5v)+0.5).
// ---------------------------------------------------------------------------
__global__ void __launch_bounds__(LT, 1) lstm_kernel(
    const float* __restrict__ Wih1, const float* __restrict__ Whh1,
    const float* __restrict__ Wih2, const float* __restrict__ Whh2,
    const float* __restrict__ bih2, const float* __restrict__ bhh2,
    const float* __restrict__ Wout, const float* __restrict__ bout,
    float* __restrict__ out)
{
    const int tid = threadIdx.x;
    const int e   = tid >> 3;
    const int sub = tid & 7;
    const int q   = sub >> 1;
    const int hf  = sub & 1;
    const int row = q * HH + e;
    const unsigned gmask = 0xFFu << ((tid & 31) & 24);   // this lane's 8-lane group
    const bool fullwarp = (tid < 384);                   // warp 12 has 16 lanes
    const unsigned wmask = fullwarp ? 0xFFFFFFFFu : 0x0000FFFFu;

    // activation: act = ka * tanh(kb*v) + kc  (tanh for g; sigmoid otherwise)
    const float ka = (q == 2) ? 1.f : 0.5f;
    const float kb = (q == 2) ? 1.f : 0.5f;
    const float kc = (q == 2) ? 0.f : 0.5f;

    // ---- register-resident weights (half rows, f32x2 packed, zero-padded) ----
    unsigned long long wh1[13], wi2[13], wh2[13];
    {
        const float* a = Whh1 + row * HH;
        const float* b = Wih2 + row * HH;
        const float* c = Whh2 + row * HH;
        #pragma unroll
        for (int k = 0; k < 13; k++){
            int i0 = 26 * hf + 2 * k, i1 = i0 + 1;
            float a0 = (i0 < HH) ? a[i0] : 0.f, a1 = (i1 < HH) ? a[i1] : 0.f;
            float b0 = (i0 < HH) ? b[i0] : 0.f, b1 = (i1 < HH) ? b[i1] : 0.f;
            float c0 = (i0 < HH) ? c[i0] : 0.f, c1v = (i1 < HH) ? c[i1] : 0.f;
            wh1[k] = pk2(a0, a1);
            wi2[k] = pk2(b0, b1);
            wh2[k] = pk2(c0, c1v);
        }
    }
    const float werr   = Wih1[row * 8 + 7];
    const float b2     = bih2[row] + bhh2[row];
    const float bo     = bout[0];
    const float wout_e = Wout[e];

    __shared__ __align__(16) float sh1[64];         // single-buffered (see proof in C)
    __shared__ __align__(16) float sh2[2][64];      // ping-pong
    __shared__ __align__(16) float sh_part[16];     // 13 warp partials + zero pad
    if (tid < 64){ sh1[tid] = 0.f; sh2[0][tid] = 0.f; sh2[1][tid] = 0.f; }
    if (tid < 16) sh_part[tid] = 0.f;               // indices 13..15 stay zero

    float c1 = 0.f, c2 = 0.f, err = 0.f;
    float s1pre  = g_P[row];                        // P(0) + Whh1@h1(-1)=0
    float ad_cur = g_P[RR];
    __syncthreads();

    int cb = 0;
    for (int t = 0; t < TT; t++){
        const int pb = cb ^ 1;

        // prefetch next step's P row + act_dist (consumed in B / next C)
        const int tn = (t + 1 < TT) ? (t + 1) : t;
        const float p_next  = g_P[(size_t)tn * PC + row];
        const float ad_next = g_P[(size_t)tn * PC + RR];

        // ============ phase A: layer-1 activation + cell (short) ============
        {
            float v = fmaf(werr, err, s1pre);
            float act = fmaf(ka, tanhap(kb * v), kc);

            float g1 = __shfl_xor_sync(gmask, act, 2);
            float g2 = __shfl_xor_sync(gmask, act, 4);
            float g3 = __shfl_xor_sync(gmask, g1, 4);
            float gi, gf, gg, go;
            if      (q == 0){ gi = act; gf = g1;  gg = g2;  go = g3;  }
            else if (q == 1){ gi = g1;  gf = act; gg = g3;  go = g2;  }
            else if (q == 2){ gi = g2;  gf = g3;  gg = act; go = g1;  }
            else            { gi = g3;  gf = g2;  gg = g1;  go = act; }
            c1 = fmaf(gf, c1, gi * gg);
            float h1v = go * tanhap(c1);
            if (sub == 0) sh1[e] = h1v;
        }
        __syncthreads();

        // ====== phase B: layer-2 gates+cell AND pre-dot for next layer-1 ======
        float s1pre_next;
        {
            unsigned long long a0 = 0ull, a1 = 0ull, d0 = 0ull, d1 = 0ull;
            unsigned long long p0 = 0ull, p1 = 0ull;
            const float* hb1 = sh1 + 26 * hf;
            const float* hb2 = sh2[pb] + 26 * hf;
            #pragma unroll
            for (int k = 0; k < 13; k++){
                unsigned long long u = *(const unsigned long long*)(hb1 + 2*k);
                unsigned long long w = *(const unsigned long long*)(hb2 + 2*k);
                if (k & 1){ fma2(a1, wi2[k], u); fma2(d1, wh2[k], w); fma2(p1, wh1[k], u); }
                else      { fma2(a0, wi2[k], u); fma2(d0, wh2[k], w); fma2(p0, wh1[k], u); }
            }
            float s = (upksum(a0) + upksum(a1)) + (upksum(d0) + upksum(d1));
            s += __shfl_xor_sync(gmask, s, 1);
            float sp = upksum(p0) + upksum(p1);
            sp += __shfl_xor_sync(gmask, sp, 1);
            s1pre_next = sp + p_next;               // Whh1@h1(t) + P(t+1)

            float v = s + b2;
            float act = fmaf(ka, tanhap(kb * v), kc);

            float g1 = __shfl_xor_sync(gmask, act, 2);
            float g2 = __shfl_xor_sync(gmask, act, 4);
            float g3 = __shfl_xor_sync(gmask, g1, 4);
            float gi, gf, gg, go;
            if      (q == 0){ gi = act; gf = g1;  gg = g2;  go = g3;  }
            else if (q == 1){ gi = g1;  gf = act; gg = g3;  go = g2;  }
            else if (q == 2){ gi = g2;  gf = g3;  gg = act; go = g1;  }
            else            { gi = g3;  gf = g2;  gg = g1;  go = act; }
            c2 = fmaf(gf, c2, gi * gg);
            float h2v = go * tanhap(c2);
            if (sub == 0) sh2[cb][e] = h2v;

            // ---- warp-level y partial: sum wout_e*h2v over this warp's elements
            float py = wout_e * h2v;                // identical in all 8 group lanes
            py += __shfl_xor_sync(wmask, py, 8);    // + neighbor element
            if (fullwarp) py += __shfl_xor_sync(0xFFFFFFFFu, py, 16);  // + next pair
            if ((tid & 31) == 0) sh_part[tid >> 5] = py;
        }
        __syncthreads();

        // ====== phase C: y + err from 13 partials (redundant, no barrier) ======
        // sh_part reads finish before bar1(t+1), which precedes the B(t+1)
        // writes; sh1 single-buffering is safe for the same reason.
        {
            unsigned long long s0 = 0ull, s1 = 0ull;
            const unsigned long long* pp = (const unsigned long long*)sh_part;
            #pragma unroll
            for (int k = 0; k < 7; k++){
                if (k & 1) add2(s1, pp[k]); else add2(s0, pp[k]);
            }
            float y = (upksum(s0) + upksum(s1)) + bo;
            if (tid == 0) out[t] = y;
            err = fmaf(0.9f, err, 0.1f * (ad_cur - y));
        }

        s1pre = s1pre_next; ad_cur = ad_next; cb ^= 1;
    }
}

extern "C" void kernel_launch(void* const* d_in, const int* in_sizes, int n_in,
                              void* d_out, int out_size)
{
    const float* x    = (const float*)d_in[0];
    const float* Wih1 = (const float*)d_in[1];
    const float* Whh1 = (const float*)d_in[2];
    const float* bih1 = (const float*)d_in[3];
    const float* bhh1 = (const float*)d_in[4];
    const float* Wih2 = (const float*)d_in[5];
    const float* Whh2 = (const float*)d_in[6];
    const float* bih2 = (const float*)d_in[7];
    const float* bhh2 = (const float*)d_in[8];
    const float* Wout = (const float*)d_in[9];
    const float* bout = (const float*)d_in[10];
    float* out = (float*)d_out;

    precompute_kernel<<<TT, PNT>>>(x, Wih1, bih1, bhh1);
    lstm_kernel<<<1, LT>>>(Wih1, Whh1, Wih2, Whh2, bih2, bhh2, Wout, bout, out);
}

// round 15
// speedup vs baseline: 2.0149x; 1.2846x over previous
#include <cuda_runtime.h>

#define TT 65536
#define HH 50
#define RR 200      // 4*H gate rows
#define PC 208      // padded row stride of precompute buffer (floats)
#define PNT 224     // precompute threads
#define LT 400      // lstm threads: 50 elements x 4 gates x 2 halves
#define HB 28       // padded half size (28 floats = 112B, 16B-aligned halves)

// Precomputed: P[t][0..199] = W_ih1[:, :7] @ x_t[:7] + b_ih1 + b_hh1 ; P[t][200] = x_t[7]
__device__ float g_P[(size_t)TT * PC];

static __device__ __forceinline__ unsigned long long pk2(float a, float b){
    unsigned long long r; asm("mov.b64 %0, {%1, %2};" : "=l"(r) : "f"(a), "f"(b)); return r;
}
static __device__ __forceinline__ void fma2(unsigned long long& acc, unsigned long long a, unsigned long long b){
    asm("fma.rn.f32x2 %0, %1, %2, %0;" : "+l"(acc) : "l"(a), "l"(b));
}
static __device__ __forceinline__ void add2(unsigned long long& acc, unsigned long long a){
    asm("add.rn.f32x2 %0, %0, %1;" : "+l"(acc) : "l"(a));
}
static __device__ __forceinline__ float upksum(unsigned long long v){
    float x, y; asm("mov.b64 {%0, %1}, %2;" : "=f"(x), "=f"(y) : "l"(v)); return x + y;
}
static __device__ __forceinline__ float tanhap(float x){
    float r; asm("tanh.approx.f32 %0, %1;" : "=f"(r) : "f"(x)); return r;
}

// ---------------------------------------------------------------------------
// Kernel 1: parallel precompute of the err-independent part of layer-1 gates.
// ---------------------------------------------------------------------------
__global__ void precompute_kernel(const float* __restrict__ x,
                                  const float* __restrict__ Wih1,
                                  const float* __restrict__ bih1,
                                  const float* __restrict__ bhh1)
{
    int t = blockIdx.x;
    int j = threadIdx.x;
    const float* xr = x + t * 8;
    if (j < RR){
        float acc = bih1[j] + bhh1[j];
        const float* w = Wih1 + j * 8;
        #pragma unroll
        for (int k = 0; k < 7; k++) acc = fmaf(w[k], xr[k], acc);
        g_P[(size_t)t * PC + j] = acc;
    } else if (j == RR){
        g_P[(size_t)t * PC + RR] = xr[7];   // act_dist
    }
}

// ---------------------------------------------------------------------------
// Kernel 2: persistent single-block sequential LSTM scan.
// Thread tid = e*8 + q*2 + hf. Halves are 28-wide (16B-aligned) so ALL shared
// reads are LDS.128 (ulonglong2): dots cost 7 loads instead of 13.
// Butterfly uses a FIXED gate assignment (correct only in q==0 lanes, which
// include the writer sub==0); other lanes carry bounded garbage cell state
// that is never stored. y partials picked from group-base lanes via idx-shfl.
// 2 __syncthreads per step.
// ---------------------------------------------------------------------------
__global__ void __launch_bounds__(LT, 1) lstm_kernel(
    const float* __restrict__ Wih1, const float* __restrict__ Whh1,
    const float* __restrict__ Wih2, const float* __restrict__ Whh2,
    const float* __restrict__ bih2, const float* __restrict__ bhh2,
    const float* __restrict__ Wout, const float* __restrict__ bout,
    float* __restrict__ out)
{
    const int tid = threadIdx.x;
    const int e   = tid >> 3;
    const int sub = tid & 7;
    const int q   = sub >> 1;
    const int hf  = sub & 1;
    const int row = q * HH + e;
    const int wid = tid >> 5;
    const bool fullwarp = (tid < 384);                   // warp 12 has 16 lanes
    const unsigned wmask = fullwarp ? 0xFFFFFFFFu : 0x0000FFFFu;
    const unsigned gmask = 0xFFu << ((tid & 31) & 24);   // this lane's 8-lane group

    // activation: act = ka * tanh(ka*v) + kc  (tanh for g; sigmoid otherwise)
    const float ka = (q == 2) ? 1.f : 0.5f;
    const float kc = (q == 2) ? 0.f : 0.5f;

    // ---- register-resident weights: 28-wide half rows, f32x2, zero-padded ----
    unsigned long long wh1[14], wi2[14], wh2[14];
    {
        const float* a = Whh1 + row * HH;
        const float* b = Wih2 + row * HH;
        const float* c = Whh2 + row * HH;
        #pragma unroll
        for (int k = 0; k < 14; k++){
            int i0 = HB * hf + 2 * k, i1 = i0 + 1;
            float a0 = (i0 < HH) ? a[i0] : 0.f, a1 = (i1 < HH) ? a[i1] : 0.f;
            float b0 = (i0 < HH) ? b[i0] : 0.f, b1 = (i1 < HH) ? b[i1] : 0.f;
            float c0 = (i0 < HH) ? c[i0] : 0.f, c1v = (i1 < HH) ? c[i1] : 0.f;
            wh1[k] = pk2(a0, a1);
            wi2[k] = pk2(b0, b1);
            wh2[k] = pk2(c0, c1v);
        }
    }
    const float werr   = Wih1[row * 8 + 7];
    const float b2     = bih2[row] + bhh2[row];
    const float bo     = bout[0];
    const float wout_e = Wout[e];

    __shared__ __align__(16) float sh1[64];         // single-buffered
    __shared__ __align__(16) float sh2[2][64];      // ping-pong
    __shared__ __align__(16) float sh_part[16];     // 13 warp partials + zero pad
    if (tid < 64){ sh1[tid] = 0.f; sh2[0][tid] = 0.f; sh2[1][tid] = 0.f; }
    if (tid < 16) sh_part[tid] = 0.f;               // indices 13..15 stay zero

    float c1 = 0.f, c2 = 0.f, err = 0.f;
    float s1pre  = g_P[row];                        // P(0) + Whh1@h1(-1)=0
    float ad_cur = g_P[RR];
    __syncthreads();

    int cb = 0;
    for (int t = 0; t < TT; t++){
        const int pb = cb ^ 1;

        // prefetch next step's P row + act_dist (consumed in B / next C)
        const int tn = (t + 1 < TT) ? (t + 1) : t;
        const float p_next  = g_P[(size_t)tn * PC + row];
        const float ad_next = g_P[(size_t)tn * PC + RR];

        // ============ phase A: layer-1 activation + cell (no LDS) ============
        {
            float v = fmaf(werr, err, s1pre);
            float act = fmaf(ka, tanhap(ka * v), kc);

            // fixed assignment: correct in q==0 lanes (incl. writer sub==0)
            float g1 = __shfl_xor_sync(gmask, act, 2);
            float g2 = __shfl_xor_sync(gmask, act, 4);
            float g3 = __shfl_xor_sync(gmask, g1, 4);
            c1 = fmaf(g1, c1, act * g2);            // f*c + i*g (q==0 view)
            float h1v = g3 * tanhap(c1);            // o * tanh(c)
            if (sub == 0) sh1[e] = h1v;
        }
        __syncthreads();

        // ====== phase B: layer-2 gates+cell AND pre-dot for next layer-1 ======
        float s1pre_next;
        {
            unsigned long long a0 = 0ull, a1 = 0ull, d0 = 0ull, d1 = 0ull;
            unsigned long long p0 = 0ull, p1 = 0ull;
            const ulonglong2* hb1 = (const ulonglong2*)(sh1 + HB * hf);
            const ulonglong2* hb2 = (const ulonglong2*)(sh2[pb] + HB * hf);
            #pragma unroll
            for (int k = 0; k < 7; k++){
                ulonglong2 u = hb1[k];
                ulonglong2 w = hb2[k];
                fma2(a0, wi2[2*k],   u.x);  fma2(a1, wi2[2*k+1], u.y);
                fma2(d0, wh2[2*k],   w.x);  fma2(d1, wh2[2*k+1], w.y);
                fma2(p0, wh1[2*k],   u.x);  fma2(p1, wh1[2*k+1], u.y);
            }
            float s = (upksum(a0) + upksum(a1)) + (upksum(d0) + upksum(d1));
            s += __shfl_xor_sync(gmask, s, 1);
            float sp = upksum(p0) + upksum(p1);
            sp += __shfl_xor_sync(gmask, sp, 1);
            s1pre_next = sp + p_next;               // Whh1@h1(t) + P(t+1)

            float v = s + b2;
            float act = fmaf(ka, tanhap(ka * v), kc);

            float g1 = __shfl_xor_sync(gmask, act, 2);
            float g2 = __shfl_xor_sync(gmask, act, 4);
            float g3 = __shfl_xor_sync(gmask, g1, 4);
            c2 = fmaf(g1, c2, act * g2);
            float h2v = g3 * tanhap(c2);
            if (sub == 0) sh2[cb][e] = h2v;

            // y partial: pick from group-base lanes (sub==0 -> correct h2v)
            float py = wout_e * h2v;
            float ys = __shfl_sync(wmask, py, 0) + __shfl_sync(wmask, py, 8);
            if (fullwarp)
                ys += __shfl_sync(wmask, py, 16) + __shfl_sync(wmask, py, 24);
            if ((tid & 31) == 0) sh_part[wid] = ys;
        }
        __syncthreads();

        // ====== phase C: y + err from partials (redundant, no barrier) ======
        // 16 floats = 4 LDS.128; entries 13..15 are zero.
        {
            unsigned long long s0 = 0ull, s1 = 0ull;
            const ulonglong2* pp = (const ulonglong2*)sh_part;
            #pragma unroll
            for (int k = 0; k < 4; k++){
                ulonglong2 v = pp[k];
                add2(s0, v.x); add2(s1, v.y);
            }
            float y = (upksum(s0) + upksum(s1)) + bo;
            if (tid == 0) out[t] = y;
            err = fmaf(0.9f, err, 0.1f * (ad_cur - y));
        }

        s1pre = s1pre_next; ad_cur = ad_next; cb ^= 1;
    }
}

extern "C" void kernel_launch(void* const* d_in, const int* in_sizes, int n_in,
                              void* d_out, int out_size)
{
    const float* x    = (const float*)d_in[0];
    const float* Wih1 = (const float*)d_in[1];
    const float* Whh1 = (const float*)d_in[2];
    const float* bih1 = (const float*)d_in[3];
    const float* bhh1 = (const float*)d_in[4];
    const float* Wih2 = (const float*)d_in[5];
    const float* Whh2 = (const float*)d_in[6];
    const float* bih2 = (const float*)d_in[7];
    const float* bhh2 = (const float*)d_in[8];
    const float* Wout = (const float*)d_in[9];
    const float* bout = (const float*)d_in[10];
    float* out = (float*)d_out;

    precompute_kernel<<<TT, PNT>>>(x, Wih1, bih1, bhh1);
    lstm_kernel<<<1, LT>>>(Wih1, Whh1, Wih2, Whh2, bih2, bhh2, Wout, bout, out);
}